// round 4
// baseline (speedup 1.0000x reference)
#include <cuda_runtime.h>

#define LRELU(v) ((v) > 0.0f ? (v) : 0.01f * (v))

static constexpr int Bb   = 512;
static constexpr int Nn   = 64;
static constexpr int Hh   = 4;
static constexpr int FOUT = 16;

// Scratch for inter-stage activations (x1, x2: [B, N, 128])
__device__ float g_x1[(size_t)Bb * Nn * 128];
__device__ float g_x2[(size_t)Bb * Nn * 128];

// ---------------------------------------------------------------------------
// Register-blocked GEMM: C[64][NC] = A(smem)[64][K] * W(global)[NC][K]^T + bias
// 256 threads: thread grid 16(tx) x 16(ty), micro-tile 4 rows x CW cols.
// Weight k-tiles staged into smem transposed [kk][n] (stride 132) so B-loads
// are contiguous float4/float2 (conflict-free).
// ---------------------------------------------------------------------------
template<int CW>
__device__ __forceinline__ void gemm_stream(
    const float* __restrict__ sA, int lda, int Kdim,
    const float* __restrict__ gW, const float* __restrict__ gBias,
    float* __restrict__ sWt, float* __restrict__ sOut, int ldo,
    bool outT, bool relu, int tx, int ty, int tid)
{
    constexpr int NC = CW * 16;
    float c[4][CW];
#pragma unroll
    for (int i = 0; i < 4; ++i)
#pragma unroll
        for (int j = 0; j < CW; ++j) c[i][j] = 0.0f;

    for (int k0 = 0; k0 < Kdim; k0 += 32) {
        __syncthreads();   // also fences previous phase's smem writes
        for (int idx = tid; idx < NC * 32; idx += 256) {
            int n  = idx >> 5;
            int kk = idx & 31;
            sWt[kk * 132 + n] = gW[(size_t)n * Kdim + k0 + kk];
        }
        __syncthreads();
#pragma unroll 8
        for (int kk = 0; kk < 32; ++kk) {
            float a[4];
#pragma unroll
            for (int i = 0; i < 4; ++i) a[i] = sA[(4 * ty + i) * lda + k0 + kk];
            float bf[CW];
            if constexpr (CW == 8) {
                float4 b0 = *(const float4*)&sWt[kk * 132 + 8 * tx];
                float4 b1 = *(const float4*)&sWt[kk * 132 + 8 * tx + 4];
                bf[0] = b0.x; bf[1] = b0.y; bf[2] = b0.z; bf[3] = b0.w;
                bf[4] = b1.x; bf[5] = b1.y; bf[6] = b1.z; bf[7] = b1.w;
            } else {
                float2 b0 = *(const float2*)&sWt[kk * 132 + 2 * tx];
                bf[0] = b0.x; bf[1] = b0.y;
            }
#pragma unroll
            for (int i = 0; i < 4; ++i)
#pragma unroll
                for (int j = 0; j < CW; ++j)
                    c[i][j] = fmaf(a[i], bf[j], c[i][j]);
        }
    }
#pragma unroll
    for (int j = 0; j < CW; ++j) {
        int col = CW * tx + j;
        float bias = gBias[col];
#pragma unroll
        for (int i = 0; i < 4; ++i) {
            float v = c[i][j] + bias;
            if (relu) v = LRELU(v);
            int row = 4 * ty + i;
            if (outT) sOut[col * ldo + row] = v;
            else      sOut[row * ldo + col] = v;
        }
    }
}

// ---------------------------------------------------------------------------
// Fused attention block: one CTA per (head h, batch b).
//   se  = lrelu(x @ Ew^T + Eb)            [64,128]
//   k   = se @ Kw^T + Kb   (stored k^T)   [128(e),64(m)] stride 68
//   q   = se @ Qw^T + Qb                  [64,128]
//   v   = lrelu(se @ Vw^T + Vb)           [64,32]
//   w   = softmax(q k^T / sqrt(128))      [64,64] -> global w_out
//   att = w @ v                           [64,32] -> x_out[b,n,h*32+o]
// ---------------------------------------------------------------------------
template<int IN_DIM>
__global__ void __launch_bounds__(256, 1)
attn_kernel(const float* __restrict__ x,
            const float* __restrict__ Ew, const float* __restrict__ Eb,
            const float* __restrict__ Kw, const float* __restrict__ Kb,
            const float* __restrict__ Qw, const float* __restrict__ Qb,
            const float* __restrict__ Vw, const float* __restrict__ Vb,
            float* __restrict__ w_out, float* __restrict__ x_out)
{
    extern __shared__ float smem[];
    const int h = blockIdx.x, b = blockIdx.y;
    const int tid = threadIdx.x, tx = tid & 15, ty = tid >> 4;

    float* s_x  = smem;                     // 64*IN_DIM  (later reused as s_w)
    float* s_se = s_x  + 64 * IN_DIM;       // 64*128
    float* s_kT = s_se + 64 * 128;          // 128*68
    float* s_q  = s_kT + 128 * 68;          // 64*128
    float* s_v  = s_q  + 64 * 128;          // 64*32
    float* s_wt = s_v  + 64 * 32;           // 32*132 staging
    float* s_w  = s_x;                      // 64*64 overlay (x dead after ph1)

    // Load input tile x[b] (coalesced float4). gemm's internal barrier fences it.
    const float* gx = x + (size_t)b * 64 * IN_DIM;
    for (int i = 4 * tid; i < 64 * IN_DIM; i += 1024)
        *(float4*)&s_x[i] = *(const float4*)&gx[i];

    // Phase 1: shared embedding
    gemm_stream<8>(s_x, IN_DIM, IN_DIM,
                   Ew + (size_t)h * 128 * IN_DIM, Eb + h * 128,
                   s_wt, s_se, 128, false, true, tx, ty, tid);
    // Phase 2: k (transposed), q, v
    gemm_stream<8>(s_se, 128, 128, Kw + (size_t)h * 128 * 128, Kb + h * 128,
                   s_wt, s_kT, 68, true, false, tx, ty, tid);
    gemm_stream<8>(s_se, 128, 128, Qw + (size_t)h * 128 * 128, Qb + h * 128,
                   s_wt, s_q, 128, false, false, tx, ty, tid);
    gemm_stream<2>(s_se, 128, 128, Vw + (size_t)h * 32 * 128, Vb + h * 32,
                   s_wt, s_v, 32, false, true, tx, ty, tid);
    __syncthreads();

    // Phase 3: scores (64x64, K=128) + row softmax. micro-tile 4x4.
    float sc[4][4];
#pragma unroll
    for (int i = 0; i < 4; ++i)
#pragma unroll
        for (int j = 0; j < 4; ++j) sc[i][j] = 0.0f;
#pragma unroll 8
    for (int kk = 0; kk < 128; ++kk) {
        float a[4];
#pragma unroll
        for (int i = 0; i < 4; ++i) a[i] = s_q[(4 * ty + i) * 128 + kk];
        float4 bb = *(const float4*)&s_kT[kk * 68 + 4 * tx];
#pragma unroll
        for (int i = 0; i < 4; ++i) {
            sc[i][0] = fmaf(a[i], bb.x, sc[i][0]);
            sc[i][1] = fmaf(a[i], bb.y, sc[i][1]);
            sc[i][2] = fmaf(a[i], bb.z, sc[i][2]);
            sc[i][3] = fmaf(a[i], bb.w, sc[i][3]);
        }
    }
    const float SCALE = 0.08838834764831845f;  // 1/sqrt(128)
    float* wg = w_out + (((size_t)h * Bb + b) * 64) * 64;
#pragma unroll
    for (int i = 0; i < 4; ++i) {
        float m = -3.0e38f;
#pragma unroll
        for (int j = 0; j < 4; ++j) { sc[i][j] *= SCALE; m = fmaxf(m, sc[i][j]); }
#pragma unroll
        for (int off = 1; off < 16; off <<= 1)
            m = fmaxf(m, __shfl_xor_sync(0xffffffffu, m, off));
        float s = 0.0f;
#pragma unroll
        for (int j = 0; j < 4; ++j) { sc[i][j] = __expf(sc[i][j] - m); s += sc[i][j]; }
#pragma unroll
        for (int off = 1; off < 16; off <<= 1)
            s += __shfl_xor_sync(0xffffffffu, s, off);
        float inv = 1.0f / s;
        float4 wv = make_float4(sc[i][0] * inv, sc[i][1] * inv,
                                sc[i][2] * inv, sc[i][3] * inv);
        int row = 4 * ty + i;
        *(float4*)&s_w[row * 64 + 4 * tx] = wv;
        *(float4*)&wg[(size_t)row * 64 + 4 * tx] = wv;
    }
    __syncthreads();

    // Phase 4: att = w @ v (64x32, K=64). micro-tile 4x2.
    float at[4][2];
#pragma unroll
    for (int i = 0; i < 4; ++i) { at[i][0] = 0.0f; at[i][1] = 0.0f; }
#pragma unroll 8
    for (int kk = 0; kk < 64; ++kk) {
        float a[4];
#pragma unroll
        for (int i = 0; i < 4; ++i) a[i] = s_w[(4 * ty + i) * 64 + kk];
        float2 bb = *(const float2*)&s_v[kk * 32 + 2 * tx];
#pragma unroll
        for (int i = 0; i < 4; ++i) {
            at[i][0] = fmaf(a[i], bb.x, at[i][0]);
            at[i][1] = fmaf(a[i], bb.y, at[i][1]);
        }
    }
#pragma unroll
    for (int i = 0; i < 4; ++i) {
        int row = 4 * ty + i;
        *(float2*)&x_out[((size_t)b * 64 + row) * 128 + h * 32 + 2 * tx] =
            make_float2(at[i][0], at[i][1]);
    }
}

// ---------------------------------------------------------------------------
// Final MLP + softmax policy head. One warp processes 2 rows at a time.
// F1 kept transposed in smem with stride 65 (conflict-free loads AND stores).
// ---------------------------------------------------------------------------
__global__ void __launch_bounds__(256)
mlp_kernel(const float* __restrict__ x,
           const float* __restrict__ F1w, const float* __restrict__ F1b,
           const float* __restrict__ F2w, const float* __restrict__ F2b,
           float* __restrict__ out)
{
    __shared__ float sF1[128 * 65];
    __shared__ float sF2[16 * 64];
    __shared__ float sB1[64];
    __shared__ float sB2[16];
    __shared__ float sx[8][2][128];

    const int tid = threadIdx.x, lane = tid & 31, warp = tid >> 5;

    for (int idx = tid; idx < 64 * 128; idx += 256) {
        int o = idx >> 7, d = idx & 127;
        sF1[d * 65 + o] = F1w[idx];          // coalesced read, conflict-free write
    }
    for (int idx = tid; idx < 16 * 64; idx += 256) sF2[idx] = F2w[idx];
    if (tid < 64) sB1[tid] = F1b[tid];
    if (tid < 16) sB2[tid] = F2b[tid];
    __syncthreads();

    const int NGRP = (Bb * Nn) / 2;          // 16384 groups of 2 rows
    for (int g = blockIdx.x * 8 + warp; g < NGRP; g += gridDim.x * 8) {
        int row0 = g * 2;
#pragma unroll
        for (int r = 0; r < 2; ++r)
            *(float4*)&sx[warp][r][lane * 4] =
                *(const float4*)&x[(size_t)(row0 + r) * 128 + lane * 4];
        __syncwarp();

        float h0[2], h1[2];
        h0[0] = h0[1] = sB1[lane];
        h1[0] = h1[1] = sB1[lane + 32];
#pragma unroll 8
        for (int d = 0; d < 128; ++d) {
            float w0 = sF1[d * 65 + lane];
            float w1 = sF1[d * 65 + 32 + lane];
#pragma unroll
            for (int r = 0; r < 2; ++r) {
                float xv = sx[warp][r][d];
                h0[r] = fmaf(xv, w0, h0[r]);
                h1[r] = fmaf(xv, w1, h1[r]);
            }
        }
#pragma unroll
        for (int r = 0; r < 2; ++r) { h0[r] = LRELU(h0[r]); h1[r] = LRELU(h1[r]); }

#pragma unroll
        for (int r = 0; r < 2; ++r) {
            float p[16];
#pragma unroll
            for (int j = 0; j < 16; ++j) {
                float t = fmaf(h0[r], sF2[j * 64 + lane],
                               h1[r] * sF2[j * 64 + 32 + lane]);
#pragma unroll
                for (int off = 16; off > 0; off >>= 1)
                    t += __shfl_xor_sync(0xffffffffu, t, off);
                p[j] = t + sB2[j];           // identical across lanes
            }
            float m = p[0];
#pragma unroll
            for (int j = 1; j < 16; ++j) m = fmaxf(m, p[j]);
            float s = 0.0f;
#pragma unroll
            for (int j = 0; j < 16; ++j) { p[j] = __expf(p[j] - m); s += p[j]; }
            float inv = 1.0f / s;
            float mine = 0.0f;               // compile-time-indexed select
#pragma unroll
            for (int j = 0; j < 16; ++j) mine = (lane == j) ? p[j] * inv : mine;
            if (lane < 16) out[(size_t)(row0 + r) * 16 + lane] = mine;
        }
        __syncwarp();
    }
}

// ---------------------------------------------------------------------------
extern "C" void kernel_launch(void* const* d_in, const int* in_sizes, int n_in,
                              void* d_out, int out_size)
{
    const float* states = (const float*)d_in[0];
    const float* E1w = (const float*)d_in[1];  const float* E1b = (const float*)d_in[2];
    const float* K1w = (const float*)d_in[3];  const float* K1b = (const float*)d_in[4];
    const float* Q1w = (const float*)d_in[5];  const float* Q1b = (const float*)d_in[6];
    const float* V1w = (const float*)d_in[7];  const float* V1b = (const float*)d_in[8];
    const float* E2w = (const float*)d_in[9];  const float* E2b = (const float*)d_in[10];
    const float* K2w = (const float*)d_in[11]; const float* K2b = (const float*)d_in[12];
    const float* Q2w = (const float*)d_in[13]; const float* Q2b = (const float*)d_in[14];
    const float* V2w = (const float*)d_in[15]; const float* V2b = (const float*)d_in[16];
    const float* F1w = (const float*)d_in[17]; const float* F1b = (const float*)d_in[18];
    const float* F2w = (const float*)d_in[19]; const float* F2b = (const float*)d_in[20];

    float* out    = (float*)d_out;
    float* policy = out;                                      // [512,64,16]
    float* w1     = out + (size_t)Bb * Nn * FOUT;             // [4,512,64,64]
    float* w2     = w1 + (size_t)Hh * Bb * Nn * Nn;           // [4,512,64,64]

    float* x1p = nullptr; float* x2p = nullptr;
    cudaGetSymbolAddress((void**)&x1p, g_x1);
    cudaGetSymbolAddress((void**)&x2p, g_x2);

    const int SMEM1 = (64*256 + 64*128 + 128*68 + 64*128 + 64*32 + 32*132) * 4;
    const int SMEM2 = (64*128 + 64*128 + 128*68 + 64*128 + 64*32 + 32*132) * 4;
    cudaFuncSetAttribute(attn_kernel<256>, cudaFuncAttributeMaxDynamicSharedMemorySize, SMEM1);
    cudaFuncSetAttribute(attn_kernel<128>, cudaFuncAttributeMaxDynamicSharedMemorySize, SMEM2);

    dim3 grid(Hh, Bb);
    attn_kernel<256><<<grid, 256, SMEM1>>>(states, E1w, E1b, K1w, K1b,
                                           Q1w, Q1b, V1w, V1b, w1, x1p);
    attn_kernel<128><<<grid, 256, SMEM2>>>(x1p, E2w, E2b, K2w, K2b,
                                           Q2w, Q2b, V2w, V2b, w2, x2p);
    mlp_kernel<<<512, 256>>>(x2p, F1w, F1b, F2w, F2b, policy);
}